// round 1
// baseline (speedup 1.0000x reference)
#include <cuda_runtime.h>

// mean-of-linear == linear-of-mean:
//   out[r] = dot(x[r], w_avg) + b_avg
// Phase 1: reduce W[10,1,10], b[10] -> g_coef[11] (w_avg[0..9], b_avg).
// Phase 2: stream x, one thread per ROW PAIR (80B = 5 x float4, 16B aligned).

__device__ float g_coef[11];

__global__ void reduce_params_kernel(const float* __restrict__ W,
                                     const float* __restrict__ b) {
    int j = threadIdx.x;
    if (j < 10) {
        float s = 0.f;
#pragma unroll
        for (int e = 0; e < 10; ++e) s += W[e * 10 + j];
        g_coef[j] = s * 0.1f;
    } else if (j == 10) {
        float s = 0.f;
#pragma unroll
        for (int e = 0; e < 10; ++e) s += b[e];
        g_coef[10] = s * 0.1f;
    }
}

__global__ __launch_bounds__(256) void forest_dot_kernel(
    const float4* __restrict__ x4,   // x viewed as float4; 5 per row-pair
    float2* __restrict__ out2,       // out viewed as float2; 1 per row-pair
    int npairs) {
    int t = blockIdx.x * blockDim.x + threadIdx.x;
    if (t >= npairs) return;

    // Broadcast coefficient loads (L1-resident after first warp).
    float c0 = g_coef[0], c1 = g_coef[1], c2 = g_coef[2], c3 = g_coef[3];
    float c4 = g_coef[4], c5 = g_coef[5], c6 = g_coef[6], c7 = g_coef[7];
    float c8 = g_coef[8], c9 = g_coef[9];
    float bias = g_coef[10];

    const float4* p = x4 + (size_t)t * 5;
    float4 v0 = p[0];
    float4 v1 = p[1];
    float4 v2 = p[2];
    float4 v3 = p[3];
    float4 v4 = p[4];

    // Row 0 = {v0.x..w, v1.x..w, v2.x, v2.y}
    float r0 = v0.x * c0;
    r0 = fmaf(v0.y, c1, r0);
    r0 = fmaf(v0.z, c2, r0);
    r0 = fmaf(v0.w, c3, r0);
    r0 = fmaf(v1.x, c4, r0);
    r0 = fmaf(v1.y, c5, r0);
    r0 = fmaf(v1.z, c6, r0);
    r0 = fmaf(v1.w, c7, r0);
    r0 = fmaf(v2.x, c8, r0);
    r0 = fmaf(v2.y, c9, r0);

    // Row 1 = {v2.z, v2.w, v3.x..w, v4.x..w}
    float r1 = v2.z * c0;
    r1 = fmaf(v2.w, c1, r1);
    r1 = fmaf(v3.x, c2, r1);
    r1 = fmaf(v3.y, c3, r1);
    r1 = fmaf(v3.z, c4, r1);
    r1 = fmaf(v3.w, c5, r1);
    r1 = fmaf(v4.x, c6, r1);
    r1 = fmaf(v4.y, c7, r1);
    r1 = fmaf(v4.z, c8, r1);
    r1 = fmaf(v4.w, c9, r1);

    out2[t] = make_float2(r0 + bias, r1 + bias);
}

extern "C" void kernel_launch(void* const* d_in, const int* in_sizes, int n_in,
                              void* d_out, int out_size) {
    const float* x = (const float*)d_in[0];   // [B, 10]
    const float* W = (const float*)d_in[1];   // [10, 1, 10]
    const float* b = (const float*)d_in[2];   // [10, 1]

    int B = in_sizes[0] / 10;                 // 4,000,000
    int npairs = B / 2;                       // B is even

    reduce_params_kernel<<<1, 32>>>(W, b);

    int threads = 256;
    int blocks = (npairs + threads - 1) / threads;
    forest_dot_kernel<<<blocks, threads>>>(
        (const float4*)x, (float2*)d_out, npairs);
}

// round 2
// speedup vs baseline: 1.0661x; 1.0661x over previous
#include <cuda_runtime.h>

// mean-of-linear == linear-of-mean:
//   out[r] = dot(x[r], w_avg) + b_avg
// Single fused kernel: each block reduces W[10,1,10], b[10] -> smem coef[11]
// (110 floats, L2-broadcast, negligible), then streams x with one thread per
// ROW PAIR (80B = 5 x float4, 16B aligned). Streaming cache hints: x and out
// are strictly single-use (176 MB), keep them out of L2's way.

__global__ __launch_bounds__(256) void forest_fused_kernel(
    const float4* __restrict__ x4,   // x viewed as float4; 5 per row-pair
    const float*  __restrict__ W,    // [10, 1, 10]
    const float*  __restrict__ b,    // [10, 1]
    float2* __restrict__ out2,       // out viewed as float2; 1 per row-pair
    int npairs) {
    __shared__ float sc[11];
    if (threadIdx.x < 11) {
        float s = 0.f;
        if (threadIdx.x < 10) {
#pragma unroll
            for (int e = 0; e < 10; ++e) s += W[e * 10 + threadIdx.x];
        } else {
#pragma unroll
            for (int e = 0; e < 10; ++e) s += b[e];
        }
        sc[threadIdx.x] = s * 0.1f;
    }
    __syncthreads();

    int t = blockIdx.x * blockDim.x + threadIdx.x;
    if (t >= npairs) return;

    float c0 = sc[0], c1 = sc[1], c2 = sc[2], c3 = sc[3], c4 = sc[4];
    float c5 = sc[5], c6 = sc[6], c7 = sc[7], c8 = sc[8], c9 = sc[9];
    float bias = sc[10];

    const float4* p = x4 + (size_t)t * 5;
    float4 v0 = __ldcs(p + 0);
    float4 v1 = __ldcs(p + 1);
    float4 v2 = __ldcs(p + 2);
    float4 v3 = __ldcs(p + 3);
    float4 v4 = __ldcs(p + 4);

    // Row 0 = {v0.x..w, v1.x..w, v2.x, v2.y}
    float r0 = v0.x * c0;
    r0 = fmaf(v0.y, c1, r0);
    r0 = fmaf(v0.z, c2, r0);
    r0 = fmaf(v0.w, c3, r0);
    r0 = fmaf(v1.x, c4, r0);
    r0 = fmaf(v1.y, c5, r0);
    r0 = fmaf(v1.z, c6, r0);
    r0 = fmaf(v1.w, c7, r0);
    r0 = fmaf(v2.x, c8, r0);
    r0 = fmaf(v2.y, c9, r0);

    // Row 1 = {v2.z, v2.w, v3.x..w, v4.x..w}
    float r1 = v2.z * c0;
    r1 = fmaf(v2.w, c1, r1);
    r1 = fmaf(v3.x, c2, r1);
    r1 = fmaf(v3.y, c3, r1);
    r1 = fmaf(v3.z, c4, r1);
    r1 = fmaf(v3.w, c5, r1);
    r1 = fmaf(v4.x, c6, r1);
    r1 = fmaf(v4.y, c7, r1);
    r1 = fmaf(v4.z, c8, r1);
    r1 = fmaf(v4.w, c9, r1);

    __stcs(out2 + t, make_float2(r0 + bias, r1 + bias));
}

extern "C" void kernel_launch(void* const* d_in, const int* in_sizes, int n_in,
                              void* d_out, int out_size) {
    const float* x = (const float*)d_in[0];   // [B, 10]
    const float* W = (const float*)d_in[1];   // [10, 1, 10]
    const float* b = (const float*)d_in[2];   // [10, 1]

    int B = in_sizes[0] / 10;                 // 4,000,000
    int npairs = B / 2;                       // B is even

    int threads = 256;
    int blocks = (npairs + threads - 1) / threads;
    forest_fused_kernel<<<blocks, threads>>>(
        (const float4*)x, W, b, (float2*)d_out, npairs);
}